// round 10
// baseline (speedup 1.0000x reference)
#include <cuda_runtime.h>
#include <cuda_bf16.h>
#include <cstdint>
#include <cstddef>

#define BB    8
#define NPER  4096
#define MDOWN 1024
#define KNN   32
#define CIN   64
#define COUT  128
#define EPSV  1e-5f

#define INFF __int_as_float(0x7f800000)

__device__ int g_knn[BB * MDOWN * KNN];

// ---------------------------------------------------------------------------
// helpers
// ---------------------------------------------------------------------------
__device__ __forceinline__ uint32_t smem_u32(const void* p) {
    uint32_t a;
    asm("{ .reg .u64 t; cvta.to.shared.u64 t, %1; cvt.u32.u64 %0, t; }" : "=r"(a) : "l"(p));
    return a;
}

__device__ __forceinline__ void ldsm4(uint32_t* r, uint32_t addr) {
    asm volatile("ldmatrix.sync.aligned.m8n8.x4.shared.b16 {%0,%1,%2,%3}, [%4];"
        : "=r"(r[0]), "=r"(r[1]), "=r"(r[2]), "=r"(r[3]) : "r"(addr));
}

__device__ __forceinline__ void mma16816(float* d, const uint32_t* a, const uint32_t* b) {
    asm volatile(
        "mma.sync.aligned.m16n8k16.row.col.f32.bf16.bf16.f32 "
        "{%0,%1,%2,%3}, {%4,%5,%6,%7}, {%8,%9}, {%0,%1,%2,%3};"
        : "+f"(d[0]), "+f"(d[1]), "+f"(d[2]), "+f"(d[3])
        : "r"(a[0]), "r"(a[1]), "r"(a[2]), "r"(a[3]), "r"(b[0]), "r"(b[1]));
}

__device__ __forceinline__ void split2(float v0, float v1, uint32_t& p0, uint32_t& p1) {
    __nv_bfloat162 h0 = __floats2bfloat162_rn(v0, v1);
    uint32_t u = *reinterpret_cast<uint32_t*>(&h0);
    float f0 = __uint_as_float(u << 16);
    float f1 = __uint_as_float(u & 0xffff0000u);
    __nv_bfloat162 h1 = __floats2bfloat162_rn(v0 - f0, v1 - f1);
    p0 = u;
    p1 = *reinterpret_cast<uint32_t*>(&h1);
}

__device__ __forceinline__ float gelu_exact(float v) {
    return 0.5f * v * (1.0f + erff(v * 0.7071067811865476f));
}

template<int NK>
__device__ __forceinline__ void gemm_tile(uint32_t a0Addr, uint32_t a1Addr,
                                          const uint32_t* bAddr, float (*d)[8][4]) {
    #pragma unroll
    for (int k = 0; k < NK; k++) {
        uint32_t a0[4], a1[4];
        ldsm4(a0, a0Addr + k * 32);
        ldsm4(a1, a1Addr + k * 32);
        #pragma unroll
        for (int jj = 0; jj < 4; jj++) {
            uint32_t bb[4];
            ldsm4(bb, bAddr[jj] + k * 32);
            mma16816(d[0][2 * jj],     a0, bb);
            mma16816(d[0][2 * jj + 1], a0, bb + 2);
            mma16816(d[1][2 * jj],     a1, bb);
            mma16816(d[1][2 * jj + 1], a1, bb + 2);
        }
    }
}

// ---------------------------------------------------------------------------
// Kernel 1: kNN via register secant-select + warp bitonic. 1 block = 1 query.
// ---------------------------------------------------------------------------
__device__ __forceinline__ unsigned long long blk_red64(
    unsigned long long v, int lane, int warp, unsigned long long* wr)
{
    #pragma unroll
    for (int o = 16; o; o >>= 1) v += __shfl_xor_sync(0xffffffffu, v, o);
    __syncthreads();
    if (lane == 0) wr[warp] = v;
    __syncthreads();
    return wr[0] + wr[1] + wr[2] + wr[3];
}

__device__ __forceinline__ unsigned long long bitonic_ce(
    unsigned long long v, int e, int j, int k)
{
    unsigned long long p = __shfl_xor_sync(0xffffffffu, v, j);
    bool up  = ((e & k) == 0);
    bool low = ((e & j) == 0);
    unsigned long long mn = (v < p) ? v : p;
    unsigned long long mx = (v < p) ? p : v;
    return (up == low) ? mn : mx;
}

__global__ __launch_bounds__(128) void knn_kernel(const float* __restrict__ pos)
{
    __shared__ unsigned long long wred[4];
    __shared__ unsigned long long cand[64];
    __shared__ int scnt;

    int blk = blockIdx.x;
    int b = blk >> 10;
    int i = blk & (MDOWN - 1);
    int t = threadIdx.x;
    int lane = t & 31, warp = t >> 5;
    const float* pbase = pos + (size_t)b * NPER * 3;

    float qx = pbase[i * 3 + 0];
    float qy = pbase[i * 3 + 1];
    float qz = pbase[i * 3 + 2];

    uint32_t vb[32];
    #pragma unroll
    for (int s = 0; s < 32; s++) {
        int p = t + s * 128;
        float dx = pbase[p * 3 + 0] - qx;
        float dy = pbase[p * 3 + 1] - qy;
        float dz = pbase[p * 3 + 2] - qz;
        vb[s] = __float_as_uint(dx * dx + dy * dy + dz * dz);
    }

    const uint32_t T1 = 0x3C23D70Au;  // 0.01
    const uint32_t T2 = 0x3D75C28Fu;  // 0.06
    const uint32_t T3 = 0x3E800000u;  // 0.25
    {
        unsigned int c1 = 0, c2 = 0, c3 = 0;
        #pragma unroll
        for (int s = 0; s < 32; s++) {
            c1 += (vb[s] < T1);
            c2 += (vb[s] < T2);
            c3 += (vb[s] < T3);
        }
        unsigned long long packed =
            (unsigned long long)c1 | ((unsigned long long)c2 << 16) |
            ((unsigned long long)c3 << 32);
        unsigned long long tot = blk_red64(packed, lane, warp, wred);
        unsigned int C1 = (unsigned int)(tot & 0xffff);
        unsigned int C2 = (unsigned int)((tot >> 16) & 0xffff);
        unsigned int C3 = (unsigned int)((tot >> 32) & 0xffff);

        uint32_t lo, hi;
        unsigned int clo, chi;
        if (C1 >= KNN)      { lo = 0;  hi = T1; clo = 0;  chi = C1; }
        else if (C2 >= KNN) { lo = T1; hi = T2; clo = C1; chi = C2; }
        else if (C3 >= KNN) { lo = T2; hi = T3; clo = C2; chi = C3; }
        else                { lo = T3; hi = 0x7f800000u; clo = C3; chi = NPER; }

        for (int it = 0; it < 12 && chi > 64 && (hi - lo) > 1; it++) {
            float frac = (48.0f - (float)clo) / (float)(chi - clo);
            frac = fminf(fmaxf(frac, 0.05f), 0.95f);
            uint32_t mid = lo + (uint32_t)((float)(hi - lo) * frac);
            if (mid <= lo) mid = lo + 1;
            if (mid >= hi) mid = hi - 1;
            unsigned int c = 0;
            #pragma unroll
            for (int s = 0; s < 32; s++) c += (vb[s] < mid);
            unsigned long long ct = blk_red64(c, lane, warp, wred);
            unsigned int cc = (unsigned int)ct;
            if (cc >= KNN) { hi = mid; chi = cc; }
            else           { lo = mid; clo = cc; }
        }

        if (t == 0) scnt = 0;
        __syncthreads();
        #pragma unroll
        for (int s = 0; s < 32; s++) {
            if (vb[s] < hi) {
                int slot = atomicAdd(&scnt, 1);
                if (slot < 64)
                    cand[slot] = ((unsigned long long)vb[s] << 32) |
                                 (unsigned)(t + s * 128);
            }
        }
        __syncthreads();
        int n = scnt; if (n > 64) n = 64;
        if (t < 64 && t >= n) cand[t] = ~0ull;
        __syncthreads();
    }

    if (warp == 0) {
        unsigned long long r0 = cand[lane];
        unsigned long long r1 = cand[lane + 32];
        #pragma unroll
        for (int k = 2; k <= 64; k <<= 1) {
            if (k == 64) {
                unsigned long long mn = (r0 < r1) ? r0 : r1;
                unsigned long long mx = (r0 < r1) ? r1 : r0;
                r0 = mn; r1 = mx;
            }
            int jstart = (k == 64) ? 16 : (k >> 1);
            for (int j = jstart; j > 0; j >>= 1) {
                r0 = bitonic_ce(r0, lane, j, k);
                r1 = bitonic_ce(r1, lane + 32, j, k);
            }
        }
        g_knn[blk * KNN + lane] = (int)(r0 & 0xffffffffu);
    }
}

// ---------------------------------------------------------------------------
// Kernel 2: persistent HMMA MLP — round-5 best config (256 thr, warp = 32x64).
// ---------------------------------------------------------------------------
#define STR1 176
#define STR2 272

#define OW1A 0
#define OW1B 22528
#define OW2A 45056
#define OW2B 79872
#define OA0  114688
#define OA1  149504
#define OPAR 184320
#define OSTAT 186880
#define SM_TOTAL 188928

#define NTILE (BB * MDOWN / 4)   // 2048

__global__ __launch_bounds__(256)
void mlp_mma_kernel(
    const float* __restrict__ x, const float* __restrict__ pos,
    const float* __restrict__ W1, const float* __restrict__ b1,
    const float* __restrict__ g1, const float* __restrict__ be1,
    const float* __restrict__ W2, const float* __restrict__ b2,
    const float* __restrict__ g2, const float* __restrict__ be2,
    float* __restrict__ xd)
{
    extern __shared__ char smc[];
    uint32_t sbase = smem_u32(smc);
    float* sP = (float*)(smc + OPAR);
    float* sStat = (float*)(smc + OSTAT);

    int t = threadIdx.x;
    int lane = t & 31, w = t >> 5;
    int mw = w & 3, nh = w >> 2;
    int g = lane >> 2, tq = lane & 3;

    if (t < 128) {
        sP[t]       = g1[t];
        sP[128 + t] = be1[t];
        sP[256 + t] = b2[t];
        sP[384 + t] = g2[t];
        sP[512 + t] = be2[t];
    }
    {
        int r = t >> 1, h = t & 1;
        #pragma unroll
        for (int kk = 0; kk < 40; kk += 2) {
            int k = h * 40 + kk;
            float v0 = (k < 67) ? W1[k * COUT + r] : 0.0f;
            float v1 = (k + 1 < 67) ? W1[(k + 1) * COUT + r] : ((k + 1 == 67) ? b1[r] : 0.0f);
            uint32_t p0, p1;
            split2(v0, v1, p0, p1);
            *(uint32_t*)(smc + OW1A + r * STR1 + k * 2) = p0;
            *(uint32_t*)(smc + OW1B + r * STR1 + k * 2) = p1;
        }
    }
    {
        int r = t >> 1, h = t & 1;
        #pragma unroll
        for (int kk = 0; kk < 64; kk += 2) {
            int k = h * 64 + kk;
            float v0 = W2[k * COUT + r];
            float v1 = W2[(k + 1) * COUT + r];
            uint32_t p0, p1;
            split2(v0, v1, p0, p1);
            *(uint32_t*)(smc + OW2A + r * STR2 + k * 2) = p0;
            *(uint32_t*)(smc + OW2B + r * STR2 + k * 2) = p1;
        }
    }

    int arow = mw * 32 + (lane & 15);
    int brow = nh * 64 + (lane & 7) + ((lane >> 4) << 3);
    int koff16 = ((lane >> 3) & 1) * 16;
    int acolg = (lane >> 4) * 16;

    uint32_t a1A = sbase + OA0 + arow * STR1 + acolg;
    uint32_t a1B = sbase + OA1 + arow * STR1 + acolg;
    uint32_t a2A = sbase + OA0 + arow * STR2 + acolg;
    uint32_t a2B = sbase + OA1 + arow * STR2 + acolg;
    uint32_t b1A[4], b1B[4], b2A[4], b2B[4];
    #pragma unroll
    for (int jj = 0; jj < 4; jj++) {
        b1A[jj] = sbase + OW1A + brow * STR1 + koff16 + jj * 16 * STR1;
        b1B[jj] = sbase + OW1B + brow * STR1 + koff16 + jj * 16 * STR1;
        b2A[jj] = sbase + OW2A + brow * STR2 + koff16 + jj * 16 * STR2;
        b2B[jj] = sbase + OW2B + brow * STR2 + koff16 + jj * 16 * STR2;
    }
    __syncthreads();

    for (int tile = blockIdx.x; tile < NTILE; tile += gridDim.x) {
        int g0 = tile * 4;

        {
            int r = t >> 1, h = t & 1;
            int p = r >> 5;
            int gpt = g0 + p;
            int b = gpt >> 10;
            int ii = gpt & (MDOWN - 1);
            int idx = g_knn[tile * 128 + r];
            const float4* xr = (const float4*)(x + ((size_t)(b * NPER + idx)) * CIN) + h * 8;
            char* rowA = smc + OA0 + r * STR1 + h * 64;
            char* rowB = smc + OA1 + r * STR1 + h * 64;
            #pragma unroll
            for (int q = 0; q < 8; q++) {
                float4 f = xr[q];
                uint32_t p0, p1;
                split2(f.x, f.y, p0, p1);
                *(uint32_t*)(rowA + q * 8)     = p0;
                *(uint32_t*)(rowB + q * 8)     = p1;
                split2(f.z, f.w, p0, p1);
                *(uint32_t*)(rowA + q * 8 + 4) = p0;
                *(uint32_t*)(rowB + q * 8 + 4) = p1;
            }
            if (h) {
                const float* pn = pos + ((size_t)(b * NPER + idx)) * 3;
                const float* pc = pos + ((size_t)(b * NPER + ii)) * 3;
                char* rA = smc + OA0 + r * STR1;
                char* rB = smc + OA1 + r * STR1;
                uint32_t p0, p1;
                split2(pn[0] - pc[0], pn[1] - pc[1], p0, p1);
                *(uint32_t*)(rA + 128) = p0;
                *(uint32_t*)(rB + 128) = p1;
                split2(pn[2] - pc[2], 1.0f, p0, p1);
                *(uint32_t*)(rA + 132) = p0;
                *(uint32_t*)(rB + 132) = p1;
                #pragma unroll
                for (int kk = 136; kk < 160; kk += 4) {
                    *(uint32_t*)(rA + kk) = 0u;
                    *(uint32_t*)(rB + kk) = 0u;
                }
            }
        }
        __syncthreads();

        float d[2][8][4];
        #pragma unroll
        for (int i = 0; i < 2; i++)
            #pragma unroll
            for (int j = 0; j < 8; j++)
                #pragma unroll
                for (int q = 0; q < 4; q++) d[i][j][q] = 0.0f;
        gemm_tile<5>(a1A, a1A + 16 * STR1, b1A, d);
        gemm_tile<5>(a1B, a1B + 16 * STR1, b1A, d);
        gemm_tile<5>(a1A, a1A + 16 * STR1, b1B, d);

        float sv[2][2], qv[2][2], muv[2][2], invv[2][2];
        #pragma unroll
        for (int i = 0; i < 2; i++)
            #pragma unroll
            for (int sub = 0; sub < 2; sub++) {
                float s = 0.0f, q = 0.0f;
                #pragma unroll
                for (int j = 0; j < 8; j++) {
                    float u0 = d[i][j][2 * sub], u1 = d[i][j][2 * sub + 1];
                    s += u0 + u1;
                    q = fmaf(u0, u0, fmaf(u1, u1, q));
                }
                s += __shfl_xor_sync(0xffffffffu, s, 1);
                s += __shfl_xor_sync(0xffffffffu, s, 2);
                q += __shfl_xor_sync(0xffffffffu, q, 1);
                q += __shfl_xor_sync(0xffffffffu, q, 2);
                sv[i][sub] = s; qv[i][sub] = q;
                if (tq == 0) {
                    int row = mw * 32 + i * 16 + g + 8 * sub;
                    *(float2*)&sStat[(nh * 128 + row) * 2] = make_float2(s, q);
                }
            }
        __syncthreads();
        #pragma unroll
        for (int i = 0; i < 2; i++)
            #pragma unroll
            for (int sub = 0; sub < 2; sub++) {
                int row = mw * 32 + i * 16 + g + 8 * sub;
                float2 o = *(float2*)&sStat[((nh ^ 1) * 128 + row) * 2];
                float s = sv[i][sub] + o.x, q = qv[i][sub] + o.y;
                float mu = s * (1.0f / COUT);
                float var = q * (1.0f / COUT) - mu * mu;
                muv[i][sub] = mu;
                invv[i][sub] = rsqrtf(var + EPSV);
            }
        #pragma unroll
        for (int j = 0; j < 8; j++) {
            int c = nh * 64 + j * 8 + 2 * tq;
            float2 gg = *(float2*)&sP[c];
            float2 bb = *(float2*)&sP[128 + c];
            #pragma unroll
            for (int i = 0; i < 2; i++)
                #pragma unroll
                for (int sub = 0; sub < 2; sub++) {
                    float v0 = (d[i][j][2 * sub]     - muv[i][sub]) * invv[i][sub] * gg.x + bb.x;
                    float v1 = (d[i][j][2 * sub + 1] - muv[i][sub]) * invv[i][sub] * gg.y + bb.y;
                    v0 = gelu_exact(v0);
                    v1 = gelu_exact(v1);
                    uint32_t p0, p1;
                    split2(v0, v1, p0, p1);
                    int row = mw * 32 + i * 16 + g + 8 * sub;
                    uint32_t off = row * STR2 + c * 2;
                    *(uint32_t*)(smc + OA0 + off) = p0;
                    *(uint32_t*)(smc + OA1 + off) = p1;
                }
        }
        __syncthreads();

        #pragma unroll
        for (int i = 0; i < 2; i++)
            #pragma unroll
            for (int j = 0; j < 8; j++)
                #pragma unroll
                for (int q = 0; q < 4; q++) d[i][j][q] = 0.0f;
        gemm_tile<8>(a2A, a2A + 16 * STR2, b2A, d);
        gemm_tile<8>(a2B, a2B + 16 * STR2, b2A, d);
        gemm_tile<8>(a2A, a2A + 16 * STR2, b2B, d);

        #pragma unroll
        for (int j = 0; j < 8; j++) {
            int c = nh * 64 + j * 8 + 2 * tq;
            float2 b2p = *(float2*)&sP[256 + c];
            #pragma unroll
            for (int i = 0; i < 2; i++)
                #pragma unroll
                for (int sub = 0; sub < 2; sub++) {
                    d[i][j][2 * sub]     += b2p.x;
                    d[i][j][2 * sub + 1] += b2p.y;
                }
        }
        #pragma unroll
        for (int i = 0; i < 2; i++)
            #pragma unroll
            for (int sub = 0; sub < 2; sub++) {
                float s = 0.0f, q = 0.0f;
                #pragma unroll
                for (int j = 0; j < 8; j++) {
                    float u0 = d[i][j][2 * sub], u1 = d[i][j][2 * sub + 1];
                    s += u0 + u1;
                    q = fmaf(u0, u0, fmaf(u1, u1, q));
                }
                s += __shfl_xor_sync(0xffffffffu, s, 1);
                s += __shfl_xor_sync(0xffffffffu, s, 2);
                q += __shfl_xor_sync(0xffffffffu, q, 1);
                q += __shfl_xor_sync(0xffffffffu, q, 2);
                sv[i][sub] = s; qv[i][sub] = q;
                if (tq == 0) {
                    int row = mw * 32 + i * 16 + g + 8 * sub;
                    *(float2*)&sStat[(nh * 128 + row) * 2] = make_float2(s, q);
                }
            }
        __syncthreads();
        #pragma unroll
        for (int i = 0; i < 2; i++)
            #pragma unroll
            for (int sub = 0; sub < 2; sub++) {
                int row = mw * 32 + i * 16 + g + 8 * sub;
                float2 o = *(float2*)&sStat[((nh ^ 1) * 128 + row) * 2];
                float s = sv[i][sub] + o.x, q = qv[i][sub] + o.y;
                float mu = s * (1.0f / COUT);
                float var = q * (1.0f / COUT) - mu * mu;
                muv[i][sub] = mu;
                invv[i][sub] = rsqrtf(var + EPSV);
            }

        float mn0[8], mx0[8], mn1[8], mx1[8];
        #pragma unroll
        for (int j = 0; j < 8; j++) {
            int c = nh * 64 + j * 8 + 2 * tq;
            float2 g2p  = *(float2*)&sP[384 + c];
            float2 be2p = *(float2*)&sP[512 + c];
            float a0 = INFF, a1 = -INFF, a2 = INFF, a3 = -INFF;
            #pragma unroll
            for (int i = 0; i < 2; i++)
                #pragma unroll
                for (int sub = 0; sub < 2; sub++) {
                    float v0 = (d[i][j][2 * sub]     - muv[i][sub]) * invv[i][sub] * g2p.x + be2p.x;
                    float v1 = (d[i][j][2 * sub + 1] - muv[i][sub]) * invv[i][sub] * g2p.y + be2p.y;
                    a0 = fminf(a0, v0); a1 = fmaxf(a1, v0);
                    a2 = fminf(a2, v1); a3 = fmaxf(a3, v1);
                }
            mn0[j] = a0; mx0[j] = a1; mn1[j] = a2; mx1[j] = a3;
        }
        #pragma unroll
        for (int o = 4; o <= 16; o <<= 1) {
            #pragma unroll
            for (int j = 0; j < 8; j++) {
                mn0[j] = fminf(mn0[j], __shfl_xor_sync(0xffffffffu, mn0[j], o));
                mx0[j] = fmaxf(mx0[j], __shfl_xor_sync(0xffffffffu, mx0[j], o));
                mn1[j] = fminf(mn1[j], __shfl_xor_sync(0xffffffffu, mn1[j], o));
                mx1[j] = fmaxf(mx1[j], __shfl_xor_sync(0xffffffffu, mx1[j], o));
            }
        }
        if (g == 0) {
            #pragma unroll
            for (int j = 0; j < 8; j++) {
                float o0 = fmaxf(gelu_exact(mn0[j]), gelu_exact(mx0[j]));
                float o1 = fmaxf(gelu_exact(mn1[j]), gelu_exact(mx1[j]));
                int c = nh * 64 + j * 8 + 2 * tq;
                *(float2*)&xd[(size_t)(g0 + mw) * COUT + c] = make_float2(o0, o1);
            }
        }
        __syncthreads();
    }
}

// ---------------------------------------------------------------------------
// Kernel 3: upsample (4 threads/query) + pos_down/batch_down folded in.
// ---------------------------------------------------------------------------
__global__ __launch_bounds__(256) void upsample_kernel(
    const float* __restrict__ pos, float* __restrict__ outBase,
    long long* __restrict__ outI, float* __restrict__ outUF, int mode)
{
    __shared__ float pd[MDOWN * 3];
    int b = blockIdx.y;
    const float* pbase = pos + (size_t)b * NPER * 3;
    for (int u = threadIdx.x; u < MDOWN * 3; u += 256) pd[u] = pbase[u];
    __syncthreads();

    int t = threadIdx.x;
    int q = blockIdx.x * 64 + (t >> 2);
    int part = t & 3;
    float qx = pbase[q * 3 + 0];
    float qy = pbase[q * 3 + 1];
    float qz = pbase[q * 3 + 2];
    float bd = INFF; int bj = 0;
    #pragma unroll 4
    for (int jj = 0; jj < MDOWN / 4; jj++) {
        int j = 4 * jj + part;
        float dx = qx - pd[j * 3 + 0];
        float dy = qy - pd[j * 3 + 1];
        float dz = qz - pd[j * 3 + 2];
        float d = dx * dx + dy * dy + dz * dz;
        if (d < bd) { bd = d; bj = j; }
    }
    unsigned long long key =
        ((unsigned long long)__float_as_uint(bd) << 32) | (unsigned)bj;
    {
        unsigned long long o = __shfl_xor_sync(0xffffffffu, key, 1);
        if (o < key) key = o;
        o = __shfl_xor_sync(0xffffffffu, key, 2);
        if (o < key) key = o;
    }
    if (part == 0) {
        long long res = (long long)(unsigned)(key & 0xffffffffu) + (long long)b * MDOWN;
        int gidx = b * NPER + q;
        if (mode) outI[gidx] = res;
        else      outUF[gidx] = (float)res;
    }

    if (t < 16) {
        int i = blockIdx.x * 16 + t;
        int gl = b * MDOWN + i;
        float* pdst = outBase + (size_t)BB * MDOWN * COUT + (size_t)gl * 3;
        pdst[0] = pd[i * 3 + 0];
        pdst[1] = pd[i * 3 + 1];
        pdst[2] = pd[i * 3 + 2];
        if (mode) {
            long long* bd2 = (long long*)((char*)outBase
                + (size_t)(BB * MDOWN * COUT + BB * MDOWN * 3) * 4);
            bd2[gl] = (long long)b;
        } else {
            outBase[(size_t)BB * MDOWN * COUT + BB * MDOWN * 3 + gl] = (float)b;
        }
    }
}

// ---------------------------------------------------------------------------
// launcher
// ---------------------------------------------------------------------------
extern "C" void kernel_launch(void* const* d_in, const int* in_sizes, int n_in,
                              void* d_out, int out_size)
{
    const float* x   = (const float*)d_in[0];
    const float* pos = (const float*)d_in[1];
    const float* W1  = (const float*)d_in[3];
    const float* b1  = (const float*)d_in[4];
    const float* g1  = (const float*)d_in[5];
    const float* be1 = (const float*)d_in[6];
    const float* W2  = (const float*)d_in[7];
    const float* b2  = (const float*)d_in[8];
    const float* g2  = (const float*)d_in[9];
    const float* be2 = (const float*)d_in[10];
    float* out = (float*)d_out;

    const int FLOAT_FULL = BB * MDOWN * COUT + BB * MDOWN * 3 + BB * MDOWN + BB * NPER;
    const int I64_FULL   = BB * MDOWN * COUT + BB * MDOWN * 3 + 2 * (BB * MDOWN + BB * NPER);
    int mode;
    if (out_size == I64_FULL)        mode = 1;
    else if (out_size >= FLOAT_FULL) mode = 0;
    else                             mode = 2;

    static int smem_set = 0;
    if (!smem_set) {
        cudaFuncSetAttribute(mlp_mma_kernel,
            cudaFuncAttributeMaxDynamicSharedMemorySize, SM_TOTAL);
        smem_set = 1;
    }

    knn_kernel<<<BB * MDOWN, 128>>>(pos);

    mlp_mma_kernel<<<152, 256, SM_TOTAL>>>(
        x, pos, W1, b1, g1, be1, W2, b2, g2, be2, out);

    if (mode != 2) {
        long long* outUI = (long long*)((char*)d_out
            + (size_t)(BB * MDOWN * COUT + BB * MDOWN * 3) * 4
            + (size_t)(BB * MDOWN) * 8);
        float* outUF = out + (size_t)(BB * MDOWN * COUT + BB * MDOWN * 3 + BB * MDOWN);
        dim3 ug(NPER / 64, BB);
        upsample_kernel<<<ug, 256>>>(pos, out, outUI, outUF, mode);
    }
}

// round 11
// speedup vs baseline: 1.0031x; 1.0031x over previous
#include <cuda_runtime.h>
#include <cuda_bf16.h>
#include <cstdint>
#include <cstddef>

#define BB    8
#define NPER  4096
#define MDOWN 1024
#define KNN   32
#define CIN   64
#define COUT  128
#define EPSV  1e-5f

#define INFF __int_as_float(0x7f800000)

__device__ int g_knn[BB * MDOWN * KNN];

// ---------------------------------------------------------------------------
// helpers
// ---------------------------------------------------------------------------
__device__ __forceinline__ uint32_t smem_u32(const void* p) {
    uint32_t a;
    asm("{ .reg .u64 t; cvta.to.shared.u64 t, %1; cvt.u32.u64 %0, t; }" : "=r"(a) : "l"(p));
    return a;
}

__device__ __forceinline__ void ldsm4(uint32_t* r, uint32_t addr) {
    asm volatile("ldmatrix.sync.aligned.m8n8.x4.shared.b16 {%0,%1,%2,%3}, [%4];"
        : "=r"(r[0]), "=r"(r[1]), "=r"(r[2]), "=r"(r[3]) : "r"(addr));
}

__device__ __forceinline__ void mma16816(float* d, const uint32_t* a, const uint32_t* b) {
    asm volatile(
        "mma.sync.aligned.m16n8k16.row.col.f32.bf16.bf16.f32 "
        "{%0,%1,%2,%3}, {%4,%5,%6,%7}, {%8,%9}, {%0,%1,%2,%3};"
        : "+f"(d[0]), "+f"(d[1]), "+f"(d[2]), "+f"(d[3])
        : "r"(a[0]), "r"(a[1]), "r"(a[2]), "r"(a[3]), "r"(b[0]), "r"(b[1]));
}

__device__ __forceinline__ void split2(float v0, float v1, uint32_t& p0, uint32_t& p1) {
    __nv_bfloat162 h0 = __floats2bfloat162_rn(v0, v1);
    uint32_t u = *reinterpret_cast<uint32_t*>(&h0);
    float f0 = __uint_as_float(u << 16);
    float f1 = __uint_as_float(u & 0xffff0000u);
    __nv_bfloat162 h1 = __floats2bfloat162_rn(v0 - f0, v1 - f1);
    p0 = u;
    p1 = *reinterpret_cast<uint32_t*>(&h1);
}

__device__ __forceinline__ float gelu_exact(float v) {
    return 0.5f * v * (1.0f + erff(v * 0.7071067811865476f));
}

template<int NK>
__device__ __forceinline__ void gemm_tile(uint32_t a0Addr, uint32_t a1Addr,
                                          const uint32_t* bAddr, float (*d)[8][4]) {
    #pragma unroll
    for (int k = 0; k < NK; k++) {
        uint32_t a0[4], a1[4];
        ldsm4(a0, a0Addr + k * 32);
        ldsm4(a1, a1Addr + k * 32);
        #pragma unroll
        for (int jj = 0; jj < 4; jj++) {
            uint32_t bb[4];
            ldsm4(bb, bAddr[jj] + k * 32);
            mma16816(d[0][2 * jj],     a0, bb);
            mma16816(d[0][2 * jj + 1], a0, bb + 2);
            mma16816(d[1][2 * jj],     a1, bb);
            mma16816(d[1][2 * jj + 1], a1, bb + 2);
        }
    }
}

// ---------------------------------------------------------------------------
// Kernel 1: kNN via register secant-select + warp bitonic. 1 block = 1 query.
// ---------------------------------------------------------------------------
__device__ __forceinline__ unsigned long long blk_red64(
    unsigned long long v, int lane, int warp, unsigned long long* wr)
{
    #pragma unroll
    for (int o = 16; o; o >>= 1) v += __shfl_xor_sync(0xffffffffu, v, o);
    __syncthreads();
    if (lane == 0) wr[warp] = v;
    __syncthreads();
    return wr[0] + wr[1] + wr[2] + wr[3];
}

__device__ __forceinline__ unsigned long long bitonic_ce(
    unsigned long long v, int e, int j, int k)
{
    unsigned long long p = __shfl_xor_sync(0xffffffffu, v, j);
    bool up  = ((e & k) == 0);
    bool low = ((e & j) == 0);
    unsigned long long mn = (v < p) ? v : p;
    unsigned long long mx = (v < p) ? p : v;
    return (up == low) ? mn : mx;
}

__global__ __launch_bounds__(128) void knn_kernel(const float* __restrict__ pos)
{
    __shared__ unsigned long long wred[4];
    __shared__ unsigned long long cand[64];
    __shared__ int scnt;

    int blk = blockIdx.x;
    int b = blk >> 10;
    int i = blk & (MDOWN - 1);
    int t = threadIdx.x;
    int lane = t & 31, warp = t >> 5;
    const float* pbase = pos + (size_t)b * NPER * 3;

    float qx = pbase[i * 3 + 0];
    float qy = pbase[i * 3 + 1];
    float qz = pbase[i * 3 + 2];

    uint32_t vb[32];
    #pragma unroll
    for (int s = 0; s < 32; s++) {
        int p = t + s * 128;
        float dx = pbase[p * 3 + 0] - qx;
        float dy = pbase[p * 3 + 1] - qy;
        float dz = pbase[p * 3 + 2] - qz;
        vb[s] = __float_as_uint(dx * dx + dy * dy + dz * dz);
    }

    const uint32_t T1 = 0x3C23D70Au;  // 0.01
    const uint32_t T2 = 0x3D75C28Fu;  // 0.06
    const uint32_t T3 = 0x3E800000u;  // 0.25
    {
        unsigned int c1 = 0, c2 = 0, c3 = 0;
        #pragma unroll
        for (int s = 0; s < 32; s++) {
            c1 += (vb[s] < T1);
            c2 += (vb[s] < T2);
            c3 += (vb[s] < T3);
        }
        unsigned long long packed =
            (unsigned long long)c1 | ((unsigned long long)c2 << 16) |
            ((unsigned long long)c3 << 32);
        unsigned long long tot = blk_red64(packed, lane, warp, wred);
        unsigned int C1 = (unsigned int)(tot & 0xffff);
        unsigned int C2 = (unsigned int)((tot >> 16) & 0xffff);
        unsigned int C3 = (unsigned int)((tot >> 32) & 0xffff);

        uint32_t lo, hi;
        unsigned int clo, chi;
        if (C1 >= KNN)      { lo = 0;  hi = T1; clo = 0;  chi = C1; }
        else if (C2 >= KNN) { lo = T1; hi = T2; clo = C1; chi = C2; }
        else if (C3 >= KNN) { lo = T2; hi = T3; clo = C2; chi = C3; }
        else                { lo = T3; hi = 0x7f800000u; clo = C3; chi = NPER; }

        for (int it = 0; it < 12 && chi > 64 && (hi - lo) > 1; it++) {
            float frac = (48.0f - (float)clo) / (float)(chi - clo);
            frac = fminf(fmaxf(frac, 0.05f), 0.95f);
            uint32_t mid = lo + (uint32_t)((float)(hi - lo) * frac);
            if (mid <= lo) mid = lo + 1;
            if (mid >= hi) mid = hi - 1;
            unsigned int c = 0;
            #pragma unroll
            for (int s = 0; s < 32; s++) c += (vb[s] < mid);
            unsigned long long ct = blk_red64(c, lane, warp, wred);
            unsigned int cc = (unsigned int)ct;
            if (cc >= KNN) { hi = mid; chi = cc; }
            else           { lo = mid; clo = cc; }
        }

        if (t == 0) scnt = 0;
        __syncthreads();
        #pragma unroll
        for (int s = 0; s < 32; s++) {
            if (vb[s] < hi) {
                int slot = atomicAdd(&scnt, 1);
                if (slot < 64)
                    cand[slot] = ((unsigned long long)vb[s] << 32) |
                                 (unsigned)(t + s * 128);
            }
        }
        __syncthreads();
        int n = scnt; if (n > 64) n = 64;
        if (t < 64 && t >= n) cand[t] = ~0ull;
        __syncthreads();
    }

    if (warp == 0) {
        unsigned long long r0 = cand[lane];
        unsigned long long r1 = cand[lane + 32];
        #pragma unroll
        for (int k = 2; k <= 64; k <<= 1) {
            if (k == 64) {
                unsigned long long mn = (r0 < r1) ? r0 : r1;
                unsigned long long mx = (r0 < r1) ? r1 : r0;
                r0 = mn; r1 = mx;
            }
            int jstart = (k == 64) ? 16 : (k >> 1);
            for (int j = jstart; j > 0; j >>= 1) {
                r0 = bitonic_ce(r0, lane, j, k);
                r1 = bitonic_ce(r1, lane + 32, j, k);
            }
        }
        g_knn[blk * KNN + lane] = (int)(r0 & 0xffffffffu);
    }
}

// ---------------------------------------------------------------------------
// Kernel 2: persistent HMMA MLP — round-5 best config (256 thr, warp = 32x64).
// ---------------------------------------------------------------------------
#define STR1 176
#define STR2 272

#define OW1A 0
#define OW1B 22528
#define OW2A 45056
#define OW2B 79872
#define OA0  114688
#define OA1  149504
#define OPAR 184320
#define OSTAT 186880
#define SM_TOTAL 188928

#define NTILE (BB * MDOWN / 4)   // 2048

__global__ __launch_bounds__(256)
void mlp_mma_kernel(
    const float* __restrict__ x, const float* __restrict__ pos,
    const float* __restrict__ W1, const float* __restrict__ b1,
    const float* __restrict__ g1, const float* __restrict__ be1,
    const float* __restrict__ W2, const float* __restrict__ b2,
    const float* __restrict__ g2, const float* __restrict__ be2,
    float* __restrict__ xd)
{
    extern __shared__ char smc[];
    uint32_t sbase = smem_u32(smc);
    float* sP = (float*)(smc + OPAR);
    float* sStat = (float*)(smc + OSTAT);

    int t = threadIdx.x;
    int lane = t & 31, w = t >> 5;
    int mw = w & 3, nh = w >> 2;
    int g = lane >> 2, tq = lane & 3;

    if (t < 128) {
        sP[t]       = g1[t];
        sP[128 + t] = be1[t];
        sP[256 + t] = b2[t];
        sP[384 + t] = g2[t];
        sP[512 + t] = be2[t];
    }
    {
        int r = t >> 1, h = t & 1;
        #pragma unroll
        for (int kk = 0; kk < 40; kk += 2) {
            int k = h * 40 + kk;
            float v0 = (k < 67) ? W1[k * COUT + r] : 0.0f;
            float v1 = (k + 1 < 67) ? W1[(k + 1) * COUT + r] : ((k + 1 == 67) ? b1[r] : 0.0f);
            uint32_t p0, p1;
            split2(v0, v1, p0, p1);
            *(uint32_t*)(smc + OW1A + r * STR1 + k * 2) = p0;
            *(uint32_t*)(smc + OW1B + r * STR1 + k * 2) = p1;
        }
    }
    {
        int r = t >> 1, h = t & 1;
        #pragma unroll
        for (int kk = 0; kk < 64; kk += 2) {
            int k = h * 64 + kk;
            float v0 = W2[k * COUT + r];
            float v1 = W2[(k + 1) * COUT + r];
            uint32_t p0, p1;
            split2(v0, v1, p0, p1);
            *(uint32_t*)(smc + OW2A + r * STR2 + k * 2) = p0;
            *(uint32_t*)(smc + OW2B + r * STR2 + k * 2) = p1;
        }
    }

    int arow = mw * 32 + (lane & 15);
    int brow = nh * 64 + (lane & 7) + ((lane >> 4) << 3);
    int koff16 = ((lane >> 3) & 1) * 16;
    int acolg = (lane >> 4) * 16;

    uint32_t a1A = sbase + OA0 + arow * STR1 + acolg;
    uint32_t a1B = sbase + OA1 + arow * STR1 + acolg;
    uint32_t a2A = sbase + OA0 + arow * STR2 + acolg;
    uint32_t a2B = sbase + OA1 + arow * STR2 + acolg;
    uint32_t b1A[4], b1B[4], b2A[4], b2B[4];
    #pragma unroll
    for (int jj = 0; jj < 4; jj++) {
        b1A[jj] = sbase + OW1A + brow * STR1 + koff16 + jj * 16 * STR1;
        b1B[jj] = sbase + OW1B + brow * STR1 + koff16 + jj * 16 * STR1;
        b2A[jj] = sbase + OW2A + brow * STR2 + koff16 + jj * 16 * STR2;
        b2B[jj] = sbase + OW2B + brow * STR2 + koff16 + jj * 16 * STR2;
    }
    __syncthreads();

    for (int tile = blockIdx.x; tile < NTILE; tile += gridDim.x) {
        int g0 = tile * 4;

        {
            int r = t >> 1, h = t & 1;
            int p = r >> 5;
            int gpt = g0 + p;
            int b = gpt >> 10;
            int ii = gpt & (MDOWN - 1);
            int idx = g_knn[tile * 128 + r];
            const float4* xr = (const float4*)(x + ((size_t)(b * NPER + idx)) * CIN) + h * 8;
            char* rowA = smc + OA0 + r * STR1 + h * 64;
            char* rowB = smc + OA1 + r * STR1 + h * 64;
            #pragma unroll
            for (int q = 0; q < 8; q++) {
                float4 f = xr[q];
                uint32_t p0, p1;
                split2(f.x, f.y, p0, p1);
                *(uint32_t*)(rowA + q * 8)     = p0;
                *(uint32_t*)(rowB + q * 8)     = p1;
                split2(f.z, f.w, p0, p1);
                *(uint32_t*)(rowA + q * 8 + 4) = p0;
                *(uint32_t*)(rowB + q * 8 + 4) = p1;
            }
            if (h) {
                const float* pn = pos + ((size_t)(b * NPER + idx)) * 3;
                const float* pc = pos + ((size_t)(b * NPER + ii)) * 3;
                char* rA = smc + OA0 + r * STR1;
                char* rB = smc + OA1 + r * STR1;
                uint32_t p0, p1;
                split2(pn[0] - pc[0], pn[1] - pc[1], p0, p1);
                *(uint32_t*)(rA + 128) = p0;
                *(uint32_t*)(rB + 128) = p1;
                split2(pn[2] - pc[2], 1.0f, p0, p1);
                *(uint32_t*)(rA + 132) = p0;
                *(uint32_t*)(rB + 132) = p1;
                #pragma unroll
                for (int kk = 136; kk < 160; kk += 4) {
                    *(uint32_t*)(rA + kk) = 0u;
                    *(uint32_t*)(rB + kk) = 0u;
                }
            }
        }
        __syncthreads();

        float d[2][8][4];
        #pragma unroll
        for (int i = 0; i < 2; i++)
            #pragma unroll
            for (int j = 0; j < 8; j++)
                #pragma unroll
                for (int q = 0; q < 4; q++) d[i][j][q] = 0.0f;
        gemm_tile<5>(a1A, a1A + 16 * STR1, b1A, d);
        gemm_tile<5>(a1B, a1B + 16 * STR1, b1A, d);
        gemm_tile<5>(a1A, a1A + 16 * STR1, b1B, d);

        float sv[2][2], qv[2][2], muv[2][2], invv[2][2];
        #pragma unroll
        for (int i = 0; i < 2; i++)
            #pragma unroll
            for (int sub = 0; sub < 2; sub++) {
                float s = 0.0f, q = 0.0f;
                #pragma unroll
                for (int j = 0; j < 8; j++) {
                    float u0 = d[i][j][2 * sub], u1 = d[i][j][2 * sub + 1];
                    s += u0 + u1;
                    q = fmaf(u0, u0, fmaf(u1, u1, q));
                }
                s += __shfl_xor_sync(0xffffffffu, s, 1);
                s += __shfl_xor_sync(0xffffffffu, s, 2);
                q += __shfl_xor_sync(0xffffffffu, q, 1);
                q += __shfl_xor_sync(0xffffffffu, q, 2);
                sv[i][sub] = s; qv[i][sub] = q;
                if (tq == 0) {
                    int row = mw * 32 + i * 16 + g + 8 * sub;
                    *(float2*)&sStat[(nh * 128 + row) * 2] = make_float2(s, q);
                }
            }
        __syncthreads();
        #pragma unroll
        for (int i = 0; i < 2; i++)
            #pragma unroll
            for (int sub = 0; sub < 2; sub++) {
                int row = mw * 32 + i * 16 + g + 8 * sub;
                float2 o = *(float2*)&sStat[((nh ^ 1) * 128 + row) * 2];
                float s = sv[i][sub] + o.x, q = qv[i][sub] + o.y;
                float mu = s * (1.0f / COUT);
                float var = q * (1.0f / COUT) - mu * mu;
                muv[i][sub] = mu;
                invv[i][sub] = rsqrtf(var + EPSV);
            }
        #pragma unroll
        for (int j = 0; j < 8; j++) {
            int c = nh * 64 + j * 8 + 2 * tq;
            float2 gg = *(float2*)&sP[c];
            float2 bb = *(float2*)&sP[128 + c];
            #pragma unroll
            for (int i = 0; i < 2; i++)
                #pragma unroll
                for (int sub = 0; sub < 2; sub++) {
                    float v0 = (d[i][j][2 * sub]     - muv[i][sub]) * invv[i][sub] * gg.x + bb.x;
                    float v1 = (d[i][j][2 * sub + 1] - muv[i][sub]) * invv[i][sub] * gg.y + bb.y;
                    v0 = gelu_exact(v0);
                    v1 = gelu_exact(v1);
                    uint32_t p0, p1;
                    split2(v0, v1, p0, p1);
                    int row = mw * 32 + i * 16 + g + 8 * sub;
                    uint32_t off = row * STR2 + c * 2;
                    *(uint32_t*)(smc + OA0 + off) = p0;
                    *(uint32_t*)(smc + OA1 + off) = p1;
                }
        }
        __syncthreads();

        #pragma unroll
        for (int i = 0; i < 2; i++)
            #pragma unroll
            for (int j = 0; j < 8; j++)
                #pragma unroll
                for (int q = 0; q < 4; q++) d[i][j][q] = 0.0f;
        gemm_tile<8>(a2A, a2A + 16 * STR2, b2A, d);
        gemm_tile<8>(a2B, a2B + 16 * STR2, b2A, d);
        gemm_tile<8>(a2A, a2A + 16 * STR2, b2B, d);

        #pragma unroll
        for (int j = 0; j < 8; j++) {
            int c = nh * 64 + j * 8 + 2 * tq;
            float2 b2p = *(float2*)&sP[256 + c];
            #pragma unroll
            for (int i = 0; i < 2; i++)
                #pragma unroll
                for (int sub = 0; sub < 2; sub++) {
                    d[i][j][2 * sub]     += b2p.x;
                    d[i][j][2 * sub + 1] += b2p.y;
                }
        }
        #pragma unroll
        for (int i = 0; i < 2; i++)
            #pragma unroll
            for (int sub = 0; sub < 2; sub++) {
                float s = 0.0f, q = 0.0f;
                #pragma unroll
                for (int j = 0; j < 8; j++) {
                    float u0 = d[i][j][2 * sub], u1 = d[i][j][2 * sub + 1];
                    s += u0 + u1;
                    q = fmaf(u0, u0, fmaf(u1, u1, q));
                }
                s += __shfl_xor_sync(0xffffffffu, s, 1);
                s += __shfl_xor_sync(0xffffffffu, s, 2);
                q += __shfl_xor_sync(0xffffffffu, q, 1);
                q += __shfl_xor_sync(0xffffffffu, q, 2);
                sv[i][sub] = s; qv[i][sub] = q;
                if (tq == 0) {
                    int row = mw * 32 + i * 16 + g + 8 * sub;
                    *(float2*)&sStat[(nh * 128 + row) * 2] = make_float2(s, q);
                }
            }
        __syncthreads();
        #pragma unroll
        for (int i = 0; i < 2; i++)
            #pragma unroll
            for (int sub = 0; sub < 2; sub++) {
                int row = mw * 32 + i * 16 + g + 8 * sub;
                float2 o = *(float2*)&sStat[((nh ^ 1) * 128 + row) * 2];
                float s = sv[i][sub] + o.x, q = qv[i][sub] + o.y;
                float mu = s * (1.0f / COUT);
                float var = q * (1.0f / COUT) - mu * mu;
                muv[i][sub] = mu;
                invv[i][sub] = rsqrtf(var + EPSV);
            }

        float mn0[8], mx0[8], mn1[8], mx1[8];
        #pragma unroll
        for (int j = 0; j < 8; j++) {
            int c = nh * 64 + j * 8 + 2 * tq;
            float2 g2p  = *(float2*)&sP[384 + c];
            float2 be2p = *(float2*)&sP[512 + c];
            float a0 = INFF, a1 = -INFF, a2 = INFF, a3 = -INFF;
            #pragma unroll
            for (int i = 0; i < 2; i++)
                #pragma unroll
                for (int sub = 0; sub < 2; sub++) {
                    float v0 = (d[i][j][2 * sub]     - muv[i][sub]) * invv[i][sub] * g2p.x + be2p.x;
                    float v1 = (d[i][j][2 * sub + 1] - muv[i][sub]) * invv[i][sub] * g2p.y + be2p.y;
                    a0 = fminf(a0, v0); a1 = fmaxf(a1, v0);
                    a2 = fminf(a2, v1); a3 = fmaxf(a3, v1);
                }
            mn0[j] = a0; mx0[j] = a1; mn1[j] = a2; mx1[j] = a3;
        }
        #pragma unroll
        for (int o = 4; o <= 16; o <<= 1) {
            #pragma unroll
            for (int j = 0; j < 8; j++) {
                mn0[j] = fminf(mn0[j], __shfl_xor_sync(0xffffffffu, mn0[j], o));
                mx0[j] = fmaxf(mx0[j], __shfl_xor_sync(0xffffffffu, mx0[j], o));
                mn1[j] = fminf(mn1[j], __shfl_xor_sync(0xffffffffu, mn1[j], o));
                mx1[j] = fmaxf(mx1[j], __shfl_xor_sync(0xffffffffu, mx1[j], o));
            }
        }
        if (g == 0) {
            #pragma unroll
            for (int j = 0; j < 8; j++) {
                float o0 = fmaxf(gelu_exact(mn0[j]), gelu_exact(mx0[j]));
                float o1 = fmaxf(gelu_exact(mn1[j]), gelu_exact(mx1[j]));
                int c = nh * 64 + j * 8 + 2 * tq;
                *(float2*)&xd[(size_t)(g0 + mw) * COUT + c] = make_float2(o0, o1);
            }
        }
        __syncthreads();
    }
}

// ---------------------------------------------------------------------------
// Kernel 3: upsample (4 threads/query) + pos_down/batch_down folded in.
// ---------------------------------------------------------------------------
__global__ __launch_bounds__(256) void upsample_kernel(
    const float* __restrict__ pos, float* __restrict__ outBase,
    long long* __restrict__ outI, float* __restrict__ outUF, int mode)
{
    __shared__ float pd[MDOWN * 3];
    int b = blockIdx.y;
    const float* pbase = pos + (size_t)b * NPER * 3;
    for (int u = threadIdx.x; u < MDOWN * 3; u += 256) pd[u] = pbase[u];
    __syncthreads();

    int t = threadIdx.x;
    int q = blockIdx.x * 64 + (t >> 2);
    int part = t & 3;
    float qx = pbase[q * 3 + 0];
    float qy = pbase[q * 3 + 1];
    float qz = pbase[q * 3 + 2];
    float bd = INFF; int bj = 0;
    #pragma unroll 4
    for (int jj = 0; jj < MDOWN / 4; jj++) {
        int j = 4 * jj + part;
        float dx = qx - pd[j * 3 + 0];
        float dy = qy - pd[j * 3 + 1];
        float dz = qz - pd[j * 3 + 2];
        float d = dx * dx + dy * dy + dz * dz;
        if (d < bd) { bd = d; bj = j; }
    }
    unsigned long long key =
        ((unsigned long long)__float_as_uint(bd) << 32) | (unsigned)bj;
    {
        unsigned long long o = __shfl_xor_sync(0xffffffffu, key, 1);
        if (o < key) key = o;
        o = __shfl_xor_sync(0xffffffffu, key, 2);
        if (o < key) key = o;
    }
    if (part == 0) {
        long long res = (long long)(unsigned)(key & 0xffffffffu) + (long long)b * MDOWN;
        int gidx = b * NPER + q;
        if (mode) outI[gidx] = res;
        else      outUF[gidx] = (float)res;
    }

    if (t < 16) {
        int i = blockIdx.x * 16 + t;
        int gl = b * MDOWN + i;
        float* pdst = outBase + (size_t)BB * MDOWN * COUT + (size_t)gl * 3;
        pdst[0] = pd[i * 3 + 0];
        pdst[1] = pd[i * 3 + 1];
        pdst[2] = pd[i * 3 + 2];
        if (mode) {
            long long* bd2 = (long long*)((char*)outBase
                + (size_t)(BB * MDOWN * COUT + BB * MDOWN * 3) * 4);
            bd2[gl] = (long long)b;
        } else {
            outBase[(size_t)BB * MDOWN * COUT + BB * MDOWN * 3 + gl] = (float)b;
        }
    }
}

// ---------------------------------------------------------------------------
// launcher
// ---------------------------------------------------------------------------
extern "C" void kernel_launch(void* const* d_in, const int* in_sizes, int n_in,
                              void* d_out, int out_size)
{
    const float* x   = (const float*)d_in[0];
    const float* pos = (const float*)d_in[1];
    const float* W1  = (const float*)d_in[3];
    const float* b1  = (const float*)d_in[4];
    const float* g1  = (const float*)d_in[5];
    const float* be1 = (const float*)d_in[6];
    const float* W2  = (const float*)d_in[7];
    const float* b2  = (const float*)d_in[8];
    const float* g2  = (const float*)d_in[9];
    const float* be2 = (const float*)d_in[10];
    float* out = (float*)d_out;

    const int FLOAT_FULL = BB * MDOWN * COUT + BB * MDOWN * 3 + BB * MDOWN + BB * NPER;
    const int I64_FULL   = BB * MDOWN * COUT + BB * MDOWN * 3 + 2 * (BB * MDOWN + BB * NPER);
    int mode;
    if (out_size == I64_FULL)        mode = 1;
    else if (out_size >= FLOAT_FULL) mode = 0;
    else                             mode = 2;

    static int smem_set = 0;
    if (!smem_set) {
        cudaFuncSetAttribute(mlp_mma_kernel,
            cudaFuncAttributeMaxDynamicSharedMemorySize, SM_TOTAL);
        smem_set = 1;
    }

    knn_kernel<<<BB * MDOWN, 128>>>(pos);

    mlp_mma_kernel<<<152, 256, SM_TOTAL>>>(
        x, pos, W1, b1, g1, be1, W2, b2, g2, be2, out);

    if (mode != 2) {
        long long* outUI = (long long*)((char*)d_out
            + (size_t)(BB * MDOWN * COUT + BB * MDOWN * 3) * 4
            + (size_t)(BB * MDOWN) * 8);
        float* outUF = out + (size_t)(BB * MDOWN * COUT + BB * MDOWN * 3 + BB * MDOWN);
        dim3 ug(NPER / 64, BB);
        upsample_kernel<<<ug, 256>>>(pos, out, outUI, outUF, mode);
    }
}